// round 7
// baseline (speedup 1.0000x reference)
#include <cuda_runtime.h>
#include <cstdint>

#define Bsz 16
#define Cch 512
#define HWs 4096
#define Lt  77
#define Dd  768
#define NHh 8
#define HDd 64

// ---------------- scratch (device globals; no allocation allowed) ----------------
__device__ float g_q[(size_t)Bsz * HWs * Cch];     // token-major [b][hw][c] (pre-LN)
__device__ float g_attn[(size_t)Bsz * HWs * Cch];  // attention output, token-major
__device__ float g_k[Bsz * Lt * Cch];              // token-major [b*l][c] (pre-LN)
__device__ float g_v[Bsz * Lt * Cch];
__device__ float g_qsum[Bsz * HWs];                // per-token sum / sumsq (atomic acc)
__device__ float g_qsq[Bsz * HWs];
__device__ float g_ksum[Bsz * Lt];
__device__ float g_ksq[Bsz * Lt];

// =====================================================================
// helpers
// =====================================================================
__device__ __forceinline__ void mma8(float* c, const uint32_t* a, const uint32_t* b) {
    asm volatile(
        "mma.sync.aligned.m16n8k8.row.col.f32.tf32.tf32.f32 "
        "{%0,%1,%2,%3}, {%4,%5,%6,%7}, {%8,%9}, {%0,%1,%2,%3};"
        : "+f"(c[0]), "+f"(c[1]), "+f"(c[2]), "+f"(c[3])
        : "r"(a[0]), "r"(a[1]), "r"(a[2]), "r"(a[3]), "r"(b[0]), "r"(b[1]));
}

__device__ __forceinline__ void cp16(uint32_t dst, const void* src) {
    asm volatile("cp.async.cg.shared.global [%0], [%1], 16;" :: "r"(dst), "l"(src));
}
__device__ __forceinline__ void cp16z(uint32_t dst, const void* src, bool pred) {
    int sz = pred ? 16 : 0;
    asm volatile("cp.async.cg.shared.global [%0], [%1], 16, %2;" :: "r"(dst), "l"(src), "r"(sz));
}
__device__ __forceinline__ void cp_commit() { asm volatile("cp.async.commit_group;"); }
__device__ __forceinline__ void cp_wait1() { asm volatile("cp.async.wait_group 1;"); }
__device__ __forceinline__ void cp_wait0() { asm volatile("cp.async.wait_group 0;"); }

#define AS_STR 36      // A smem [128][36] row-major m x k
#define BS_STR 36      // B smem [128][36] row-major n x k
#define AQ_STR 136     // q_proj A smem [32][136] k x m
#define STAGE_A (128 * AS_STR)
#define STAGE_B (128 * BS_STR)
#define STAGE_AQ (32 * AQ_STR)

// compute one k=32 chunk; A row-major [m][k] str 36, B row-major [n][k] str 36
__device__ __forceinline__ void mma_chunk(
    const uint32_t* __restrict__ As, const uint32_t* __restrict__ Bs,
    float cacc[4][4][4], int wm, int wn, int g, int tg)
{
    #pragma unroll
    for (int ks = 0; ks < 4; ks++) {
        uint32_t af[4][4], bf[4][2];
        #pragma unroll
        for (int mt = 0; mt < 4; mt++) {
            int base = (wm * 64 + mt * 16 + g) * AS_STR + ks * 8 + tg;
            af[mt][0] = As[base];
            af[mt][1] = As[base + 8 * AS_STR];
            af[mt][2] = As[base + 4];
            af[mt][3] = As[base + 8 * AS_STR + 4];
        }
        #pragma unroll
        for (int nt = 0; nt < 4; nt++) {
            int bb = (wn * 32 + nt * 8 + g) * BS_STR + ks * 8 + tg;
            bf[nt][0] = Bs[bb];
            bf[nt][1] = Bs[bb + 4];
        }
        #pragma unroll
        for (int mt = 0; mt < 4; mt++)
            #pragma unroll
            for (int nt = 0; nt < 4; nt++)
                mma8(cacc[mt][nt], af[mt], bf[nt]);
    }
}

// compute one k=32 chunk; A k-major [k][m] str 136, B row-major [n][k] str 36
__device__ __forceinline__ void mma_chunk_kmaj(
    const uint32_t* __restrict__ As, const uint32_t* __restrict__ Bs,
    float cacc[4][4][4], int wm, int wn, int g, int tg)
{
    #pragma unroll
    for (int ks = 0; ks < 4; ks++) {
        uint32_t af[4][4], bf[4][2];
        #pragma unroll
        for (int mt = 0; mt < 4; mt++) {
            int m = wm * 64 + mt * 16 + g;
            af[mt][0] = As[(ks * 8 + tg) * AQ_STR + m];
            af[mt][1] = As[(ks * 8 + tg) * AQ_STR + m + 8];
            af[mt][2] = As[(ks * 8 + tg + 4) * AQ_STR + m];
            af[mt][3] = As[(ks * 8 + tg + 4) * AQ_STR + m + 8];
        }
        #pragma unroll
        for (int nt = 0; nt < 4; nt++) {
            int bb = (wn * 32 + nt * 8 + g) * BS_STR + ks * 8 + tg;
            bf[nt][0] = Bs[bb];
            bf[nt][1] = Bs[bb + 4];
        }
        #pragma unroll
        for (int mt = 0; mt < 4; mt++)
            #pragma unroll
            for (int nt = 0; nt < 4; nt++)
                mma8(cacc[mt][nt], af[mt], bf[nt]);
    }
}

// quad-reduce (lanes sharing g, tg=0..3) then atomic accumulate row stats
__device__ __forceinline__ void stat_atomic(float s, float q, int tg, float* sumA, float* sqA) {
    s += __shfl_xor_sync(0xffffffffu, s, 1);
    s += __shfl_xor_sync(0xffffffffu, s, 2);
    q += __shfl_xor_sync(0xffffffffu, q, 1);
    q += __shfl_xor_sync(0xffffffffu, q, 2);
    if (tg == 0) { atomicAdd(sumA, s); atomicAdd(sqA, q); }
}

// =====================================================================
// zero stats accumulators
// =====================================================================
__global__ void zero_stats_kernel() {
    int i = blockIdx.x * 256 + threadIdx.x;
    if (i < Bsz * HWs) { g_qsum[i] = 0.f; g_qsq[i] = 0.f; }
    if (i < Bsz * Lt) { g_ksum[i] = 0.f; g_ksq[i] = 0.f; }
}

// =====================================================================
// KV projection (NT): C[m=token][n=c] = sum_d tf[m][d] * W[n][d] + bias[n]
// M=1232, N=512, K=768. grid (4, 10, 2) z: 0->k (+stats), 1->v.
// =====================================================================
__global__ __launch_bounds__(256, 2) void kv_proj_tc(
    const float* __restrict__ tf,
    const float* __restrict__ wk, const float* __restrict__ bk,
    const float* __restrict__ wv, const float* __restrict__ bv)
{
    const int M = Bsz * Lt;
    const float* W; const float* bias; float* out;
    if (blockIdx.z == 0) { W = wk; bias = bk; out = g_k; }
    else                 { W = wv; bias = bv; out = g_v; }

    extern __shared__ uint32_t dsm[];
    uint32_t* Asm[3] = { dsm, dsm + (STAGE_A + STAGE_B), dsm + 2 * (STAGE_A + STAGE_B) };
    uint32_t* Bsm[3] = { dsm + STAGE_A, dsm + (STAGE_A + STAGE_B) + STAGE_A,
                         dsm + 2 * (STAGE_A + STAGE_B) + STAGE_A };

    const int m0 = blockIdx.y * 128, n0 = blockIdx.x * 128;
    const int tid = threadIdx.x, lane = tid & 31, wid = tid >> 5;
    const int wm = wid & 1, wn = wid >> 1;
    const int g = lane >> 2, tg = lane & 3;
    const int r = tid >> 3, c4 = (tid & 7) << 2;
    float cacc[4][4][4] = {};

    auto load_stage = [&](int st, int k0) {
        #pragma unroll
        for (int u = 0; u < 4; u++) {
            int rr = r + u * 32;
            uint32_t da = __cvta_generic_to_shared(&Asm[st][rr * AS_STR + c4]);
            cp16z(da, tf + (size_t)(m0 + rr) * Dd + k0 + c4, (m0 + rr) < M);
            uint32_t db = __cvta_generic_to_shared(&Bsm[st][rr * BS_STR + c4]);
            cp16(db, W + (size_t)(n0 + rr) * Dd + k0 + c4);
        }
        cp_commit();
    };

    const int NCH = Dd / 32;
    load_stage(0, 0);
    load_stage(1, 32);
    for (int ch = 0; ch < NCH; ch++) {
        if (ch < NCH - 1) cp_wait1(); else cp_wait0();
        __syncthreads();
        if (ch + 2 < NCH) load_stage((ch + 2) % 3, (ch + 2) * 32);
        mma_chunk(Asm[ch % 3], Bsm[ch % 3], cacc, wm, wn, g, tg);
    }

    float s0[4] = {}, q0[4] = {}, s1[4] = {}, q1[4] = {};
    #pragma unroll
    for (int mt = 0; mt < 4; mt++) {
        #pragma unroll
        for (int nt = 0; nt < 4; nt++) {
            int m = m0 + wm * 64 + mt * 16 + g;
            int n = n0 + wn * 32 + nt * 8 + tg * 2;
            float2 bb = *(const float2*)(bias + n);
            float2 r0 = make_float2(cacc[mt][nt][0] + bb.x, cacc[mt][nt][1] + bb.y);
            float2 r1 = make_float2(cacc[mt][nt][2] + bb.x, cacc[mt][nt][3] + bb.y);
            if (m < M) *(float2*)(out + (size_t)m * Cch + n) = r0;
            if (m + 8 < M) *(float2*)(out + (size_t)(m + 8) * Cch + n) = r1;
            s0[mt] += r0.x + r0.y; q0[mt] += r0.x * r0.x + r0.y * r0.y;
            s1[mt] += r1.x + r1.y; q1[mt] += r1.x * r1.x + r1.y * r1.y;
        }
    }
    if (blockIdx.z == 0) {
        #pragma unroll
        for (int mt = 0; mt < 4; mt++) {
            int m = m0 + wm * 64 + mt * 16 + g;
            if (m < M) stat_atomic(s0[mt], q0[mt], tg, &g_ksum[m], &g_ksq[m]);
            if (m + 8 < M) stat_atomic(s1[mt], q1[mt], tg, &g_ksum[m + 8], &g_ksq[m + 8]);
        }
    }
}

// =====================================================================
// Q projection, token-major output + LN stats:
// C[m=token][n=chan] = sum_c X[c][m] * wq[n][c] + bq[n] + 0.05*pe(n,m)
// M=4096, N=512, K=512. grid (4, 32, 16).
// =====================================================================
__global__ __launch_bounds__(256, 2) void q_proj_tc(
    const float* __restrict__ x, const float* __restrict__ wq, const float* __restrict__ bq)
{
    const int b = blockIdx.z;
    const float* X = x + (size_t)b * Cch * HWs;
    float* out = g_q + (size_t)b * HWs * Cch;

    extern __shared__ uint32_t dsm[];
    uint32_t* Asm[3] = { dsm, dsm + (STAGE_AQ + STAGE_B), dsm + 2 * (STAGE_AQ + STAGE_B) };
    uint32_t* Bsm[3] = { dsm + STAGE_AQ, dsm + (STAGE_AQ + STAGE_B) + STAGE_AQ,
                         dsm + 2 * (STAGE_AQ + STAGE_B) + STAGE_AQ };

    const int m0 = blockIdx.y * 128, n0 = blockIdx.x * 128;
    const int tid = threadIdx.x, lane = tid & 31, wid = tid >> 5;
    const int wm = wid & 1, wn = wid >> 1;
    const int g = lane >> 2, tg = lane & 3;
    const int kk = tid >> 5, mc4 = (tid & 31) << 2;
    const int r = tid >> 3, c4 = (tid & 7) << 2;
    float cacc[4][4][4] = {};

    auto load_stage = [&](int st, int k0) {
        #pragma unroll
        for (int u = 0; u < 4; u++) {
            int kr = kk + u * 8;
            uint32_t da = __cvta_generic_to_shared(&Asm[st][kr * AQ_STR + mc4]);
            cp16(da, X + (size_t)(k0 + kr) * HWs + m0 + mc4);
            int rr = r + u * 32;
            uint32_t db = __cvta_generic_to_shared(&Bsm[st][rr * BS_STR + c4]);
            cp16(db, wq + (size_t)(n0 + rr) * Cch + k0 + c4);
        }
        cp_commit();
    };

    const int NCH = Cch / 32;
    load_stage(0, 0);
    load_stage(1, 32);
    for (int ch = 0; ch < NCH; ch++) {
        if (ch < NCH - 1) cp_wait1(); else cp_wait0();
        __syncthreads();
        if (ch + 2 < NCH) load_stage((ch + 2) % 3, (ch + 2) * 32);
        mma_chunk_kmaj(Asm[ch % 3], Bsm[ch % 3], cacc, wm, wn, g, tg);
    }

    const float pes = 0.05f / 63.0f;
    float s0[4] = {}, q0[4] = {}, s1[4] = {}, q1[4] = {};
    #pragma unroll
    for (int mt = 0; mt < 4; mt++) {
        #pragma unroll
        for (int nt = 0; nt < 4; nt++) {
            int m = m0 + wm * 64 + mt * 16 + g;     // token
            int n = n0 + wn * 32 + nt * 8 + tg * 2; // channel
            float2 bb = *(const float2*)(bq + n);
            bool use_x = n < (Cch / 2);
            float pe0 = pes * (float)(use_x ? (m & 63) : ((m >> 6) & 63));
            float pe1 = pes * (float)(use_x ? ((m + 8) & 63) : (((m + 8) >> 6) & 63));
            float2 r0 = make_float2(cacc[mt][nt][0] + bb.x + pe0, cacc[mt][nt][1] + bb.y + pe0);
            float2 r1 = make_float2(cacc[mt][nt][2] + bb.x + pe1, cacc[mt][nt][3] + bb.y + pe1);
            *(float2*)(out + (size_t)m * Cch + n) = r0;
            *(float2*)(out + (size_t)(m + 8) * Cch + n) = r1;
            s0[mt] += r0.x + r0.y; q0[mt] += r0.x * r0.x + r0.y * r0.y;
            s1[mt] += r1.x + r1.y; q1[mt] += r1.x * r1.x + r1.y * r1.y;
        }
    }
    #pragma unroll
    for (int mt = 0; mt < 4; mt++) {
        int m = m0 + wm * 64 + mt * 16 + g;
        size_t row = (size_t)b * HWs + m;
        stat_atomic(s0[mt], q0[mt], tg, &g_qsum[row], &g_qsq[row]);
        stat_atomic(s1[mt], q1[mt], tg, &g_qsum[row + 8], &g_qsq[row + 8]);
    }
}

// =====================================================================
// Output projection + bias + residual:
// C[m=chan][n=token] = sum_c wo[m][c] * g_attn[n][c] + bo[m] + x[b][m][n]
// M=512, N=4096, K=512. grid (32, 4, 16).
// =====================================================================
__global__ __launch_bounds__(256, 2) void o_proj_tc(
    const float* __restrict__ wo, const float* __restrict__ bo,
    const float* __restrict__ x, float* __restrict__ outp)
{
    const int b = blockIdx.z;
    const float* Bm = g_attn + (size_t)b * HWs * Cch;

    extern __shared__ uint32_t dsm[];
    uint32_t* Asm[3] = { dsm, dsm + (STAGE_A + STAGE_B), dsm + 2 * (STAGE_A + STAGE_B) };
    uint32_t* Bsm[3] = { dsm + STAGE_A, dsm + (STAGE_A + STAGE_B) + STAGE_A,
                         dsm + 2 * (STAGE_A + STAGE_B) + STAGE_A };

    const int m0 = blockIdx.y * 128, n0 = blockIdx.x * 128;
    const int tid = threadIdx.x, lane = tid & 31, wid = tid >> 5;
    const int wm = wid & 1, wn = wid >> 1;
    const int g = lane >> 2, tg = lane & 3;
    const int r = tid >> 3, c4 = (tid & 7) << 2;
    float cacc[4][4][4] = {};

    auto load_stage = [&](int st, int k0) {
        #pragma unroll
        for (int u = 0; u < 4; u++) {
            int rr = r + u * 32;
            uint32_t da = __cvta_generic_to_shared(&Asm[st][rr * AS_STR + c4]);
            cp16(da, wo + (size_t)(m0 + rr) * Cch + k0 + c4);
            uint32_t db = __cvta_generic_to_shared(&Bsm[st][rr * BS_STR + c4]);
            cp16(db, Bm + (size_t)(n0 + rr) * Cch + k0 + c4);
        }
        cp_commit();
    };

    const int NCH = Cch / 32;
    load_stage(0, 0);
    load_stage(1, 32);
    for (int ch = 0; ch < NCH; ch++) {
        if (ch < NCH - 1) cp_wait1(); else cp_wait0();
        __syncthreads();
        if (ch + 2 < NCH) load_stage((ch + 2) % 3, (ch + 2) * 32);
        mma_chunk(Asm[ch % 3], Bsm[ch % 3], cacc, wm, wn, g, tg);
    }

    #pragma unroll
    for (int mt = 0; mt < 4; mt++) {
        #pragma unroll
        for (int nt = 0; nt < 4; nt++) {
            int m = m0 + wm * 64 + mt * 16 + g;     // channel
            int n = n0 + wn * 32 + nt * 8 + tg * 2; // token
            float bo0 = bo[m], bo1 = bo[m + 8];
            size_t i0 = (size_t)b * Cch * HWs + (size_t)m * HWs + n;
            size_t i1 = (size_t)b * Cch * HWs + (size_t)(m + 8) * HWs + n;
            float2 x0 = *(const float2*)(x + i0);
            float2 x1 = *(const float2*)(x + i1);
            float2 r0 = make_float2(cacc[mt][nt][0] + bo0 + x0.x, cacc[mt][nt][1] + bo0 + x0.y);
            float2 r1 = make_float2(cacc[mt][nt][2] + bo1 + x1.x, cacc[mt][nt][3] + bo1 + x1.y);
            *(float2*)(outp + i0) = r0;
            *(float2*)(outp + i1) = r1;
        }
    }
}

// =====================================================================
// Tensor-core attention, LN(Q)/LN(K) fused, P kept in registers
// (c-frag -> a-frag via quad shuffles; no smem staging, no extra barrier).
// block = 128 q tokens x head x batch. grid (32, 8, 16), 256 threads.
// =====================================================================
#define QS_STR 68
#define KS_STR 68
#define VS_STR 68
#define ATTN_SMEM ((128 * QS_STR + 80 * KS_STR + 80 * VS_STR + 128 + 128 + 80 + 80) * 4)

__global__ __launch_bounds__(256) void attn_tc(
    const float* __restrict__ g1, const float* __restrict__ b1,
    const float* __restrict__ g2, const float* __restrict__ b2)
{
    extern __shared__ float sm[];
    float* Qs = sm;                       // [128][68]
    float* Ks = Qs + 128 * QS_STR;        // [80][68] rows 77..79 zero
    float* Vs = Ks + 80 * KS_STR;         // [80][68] rows 77..79 zero
    float* qmu = Vs + 80 * VS_STR;        // [128]
    float* qrs = qmu + 128;               // [128]
    float* kmu = qrs + 128;               // [80]
    float* krs = kmu + 80;                // [80]

    const int tid = threadIdx.x, lane = tid & 31, w = tid >> 5;
    const int g = lane >> 2, tg = lane & 3;
    const int t0 = blockIdx.x * 128, h = blockIdx.y, b = blockIdx.z;

    if (tid < 128) {
        size_t row = (size_t)b * HWs + t0 + tid;
        float s = g_qsum[row], q = g_qsq[row];
        float m = s * (1.0f / 512.0f);
        qmu[tid] = m;
        qrs[tid] = rsqrtf(q * (1.0f / 512.0f) - m * m + 1e-5f);
    } else if (tid < 128 + 80) {
        int l = tid - 128;
        float m = 0.f, r = 0.f;
        if (l < Lt) {
            size_t row = (size_t)b * Lt + l;
            float s = g_ksum[row], q = g_ksq[row];
            m = s * (1.0f / 512.0f);
            r = rsqrtf(q * (1.0f / 512.0f) - m * m + 1e-5f);
        }
        kmu[l] = m; krs[l] = r;
    }
    __syncthreads();

    // load Q (LN applied)
    const float* qb = g_q + ((size_t)b * HWs + t0) * Cch + h * HDd;
    for (int f = tid; f < 128 * 16; f += 256) {
        int t = f >> 4, dc = (f & 15) << 2;
        float4 v = *(const float4*)(qb + (size_t)t * Cch + dc);
        float4 gg = *(const float4*)(g1 + h * HDd + dc);
        float4 bb = *(const float4*)(b1 + h * HDd + dc);
        float m = qmu[t], r = qrs[t];
        float* d = Qs + t * QS_STR + dc;
        d[0] = (v.x - m) * r * gg.x + bb.x;
        d[1] = (v.y - m) * r * gg.y + bb.y;
        d[2] = (v.z - m) * r * gg.z + bb.z;
        d[3] = (v.w - m) * r * gg.w + bb.w;
    }
    // load K (LN applied; rows >= Lt zero), V raw
    const float* kb = g_k + (size_t)b * Lt * Cch + h * HDd;
    const float* vb = g_v + (size_t)b * Lt * Cch + h * HDd;
    for (int f = tid; f < 80 * 16; f += 256) {
        int l = f >> 4, dc = (f & 15) << 2;
        float* kd = Ks + l * KS_STR + dc;
        float* vd = Vs + l * VS_STR + dc;
        if (l < Lt) {
            float4 k4 = *(const float4*)(kb + (size_t)l * Cch + dc);
            float4 v4 = *(const float4*)(vb + (size_t)l * Cch + dc);
            float4 gg = *(const float4*)(g2 + h * HDd + dc);
            float4 bb = *(const float4*)(b2 + h * HDd + dc);
            float m = kmu[l], r = krs[l];
            kd[0] = (k4.x - m) * r * gg.x + bb.x;
            kd[1] = (k4.y - m) * r * gg.y + bb.y;
            kd[2] = (k4.z - m) * r * gg.z + bb.z;
            kd[3] = (k4.w - m) * r * gg.w + bb.w;
            vd[0] = v4.x; vd[1] = v4.y; vd[2] = v4.z; vd[3] = v4.w;
        } else {
            kd[0] = kd[1] = kd[2] = kd[3] = 0.f;
            vd[0] = vd[1] = vd[2] = vd[3] = 0.f;
        }
    }
    __syncthreads();

    const uint32_t* Qu = (const uint32_t*)Qs;
    const uint32_t* Ku = (const uint32_t*)Ks;
    const uint32_t* Vu = (const uint32_t*)Vs;

    // ---- S = Q K^T (warp rows w*16..w*16+15; 10 key tiles of 8)
    float sfr[10][4] = {};
    #pragma unroll
    for (int ks = 0; ks < 8; ks++) {
        uint32_t aq[4];
        int ab = (w * 16 + g) * QS_STR + ks * 8 + tg;
        aq[0] = Qu[ab];
        aq[1] = Qu[ab + 8 * QS_STR];
        aq[2] = Qu[ab + 4];
        aq[3] = Qu[ab + 8 * QS_STR + 4];
        #pragma unroll
        for (int nt = 0; nt < 10; nt++) {
            uint32_t bf[2];
            int bb = (nt * 8 + g) * KS_STR + ks * 8 + tg;
            bf[0] = Ku[bb];
            bf[1] = Ku[bb + 4];
            mma8(sfr[nt], aq, bf);
        }
    }

    // ---- softmax in registers (valid cols < 77)
    float mx0 = -1e30f, mx1 = -1e30f;
    #pragma unroll
    for (int nt = 0; nt < 10; nt++) {
        int c0 = nt * 8 + tg * 2, c1 = c0 + 1;
        if (c0 < Lt) { mx0 = fmaxf(mx0, sfr[nt][0]); mx1 = fmaxf(mx1, sfr[nt][2]); }
        if (c1 < Lt) { mx0 = fmaxf(mx0, sfr[nt][1]); mx1 = fmaxf(mx1, sfr[nt][3]); }
    }
    mx0 = fmaxf(mx0, __shfl_xor_sync(0xffffffffu, mx0, 1));
    mx0 = fmaxf(mx0, __shfl_xor_sync(0xffffffffu, mx0, 2));
    mx1 = fmaxf(mx1, __shfl_xor_sync(0xffffffffu, mx1, 1));
    mx1 = fmaxf(mx1, __shfl_xor_sync(0xffffffffu, mx1, 2));
    mx0 *= 0.125f; mx1 *= 0.125f;

    float sum0 = 0.f, sum1 = 0.f;
    #pragma unroll
    for (int nt = 0; nt < 10; nt++) {
        int c0 = nt * 8 + tg * 2, c1 = c0 + 1;
        float e00 = (c0 < Lt) ? __expf(sfr[nt][0] * 0.125f - mx0) : 0.f;
        float e01 = (c1 < Lt) ? __expf(sfr[nt][1] * 0.125f - mx0) : 0.f;
        float e10 = (c0 < Lt) ? __expf(sfr[nt][2] * 0.125f - mx1) : 0.f;
        float e11 = (c1 < Lt) ? __expf(sfr[nt][3] * 0.125f - mx1) : 0.f;
        sum0 += e00 + e01; sum1 += e10 + e11;
        sfr[nt][0] = e00; sfr[nt][1] = e01; sfr[nt][2] = e10; sfr[nt][3] = e11;
    }
    sum0 += __shfl_xor_sync(0xffffffffu, sum0, 1);
    sum0 += __shfl_xor_sync(0xffffffffu, sum0, 2);
    sum1 += __shfl_xor_sync(0xffffffffu, sum1, 1);
    sum1 += __shfl_xor_sync(0xffffffffu, sum1, 2);
    float inv0 = 1.0f / sum0, inv1 = 1.0f / sum1;

    // ---- O = P V: convert c-frag -> a-frag per key tile via quad shuffles
    float ofr[8][4] = {};
    const int src1 = (lane & ~3) | (tg >> 1);   // quad-local gather lanes
    const int src2 = src1 + 2;
    #pragma unroll
    for (int kt = 0; kt < 10; kt++) {
        float v00 = __shfl_sync(0xffffffffu, sfr[kt][0], src1);
        float v01 = __shfl_sync(0xffffffffu, sfr[kt][1], src1);
        float v20 = __shfl_sync(0xffffffffu, sfr[kt][0], src2);
        float v21 = __shfl_sync(0xffffffffu, sfr[kt][1], src2);
        float v10 = __shfl_sync(0xffffffffu, sfr[kt][2], src1);
        float v11 = __shfl_sync(0xffffffffu, sfr[kt][3], src1);
        float v30 = __shfl_sync(0xffffffffu, sfr[kt][2], src2);
        float v31 = __shfl_sync(0xffffffffu, sfr[kt][3], src2);
        bool odd = (tg & 1);
        uint32_t ap[4];
        ap[0] = __float_as_uint(odd ? v01 : v00);   // P[g][tg]
        ap[1] = __float_as_uint(odd ? v11 : v10);   // P[g+8][tg]
        ap[2] = __float_as_uint(odd ? v21 : v20);   // P[g][tg+4]
        ap[3] = __float_as_uint(odd ? v31 : v30);   // P[g+8][tg+4]
        #pragma unroll
        for (int nt = 0; nt < 8; nt++) {
            uint32_t bf[2];
            bf[0] = Vu[(kt * 8 + tg) * VS_STR + nt * 8 + g];
            bf[1] = Vu[(kt * 8 + tg + 4) * VS_STR + nt * 8 + g];
            mma8(ofr[nt], ap, bf);
        }
    }

    float* ob = g_attn + ((size_t)b * HWs + t0 + w * 16) * Cch + h * HDd;
    #pragma unroll
    for (int nt = 0; nt < 8; nt++) {
        int n = nt * 8 + tg * 2;
        float2 r0 = make_float2(ofr[nt][0] * inv0, ofr[nt][1] * inv0);
        float2 r1 = make_float2(ofr[nt][2] * inv1, ofr[nt][3] * inv1);
        *(float2*)(ob + (size_t)g * Cch + n) = r0;
        *(float2*)(ob + (size_t)(g + 8) * Cch + n) = r1;
    }
}

// =====================================================================
extern "C" void kernel_launch(void* const* d_in, const int* in_sizes, int n_in,
                              void* d_out, int out_size)
{
    const float* x  = (const float*)d_in[0];
    const float* tf = (const float*)d_in[1];
    const float* wq = (const float*)d_in[2];
    const float* bq = (const float*)d_in[3];
    const float* wk = (const float*)d_in[4];
    const float* bk = (const float*)d_in[5];
    const float* wv = (const float*)d_in[6];
    const float* bv = (const float*)d_in[7];
    const float* wo = (const float*)d_in[8];
    const float* bo = (const float*)d_in[9];
    const float* g1 = (const float*)d_in[10];
    const float* b1 = (const float*)d_in[11];
    const float* g2 = (const float*)d_in[12];
    const float* b2 = (const float*)d_in[13];
    float* out = (float*)d_out;

    const int gemm_smem = 3 * (STAGE_A + STAGE_B) * 4;     // 110592 B
    const int qgemm_smem = 3 * (STAGE_AQ + STAGE_B) * 4;   // 107520 B
    static int inited = 0;
    if (!inited) {
        cudaFuncSetAttribute(kv_proj_tc, cudaFuncAttributeMaxDynamicSharedMemorySize, gemm_smem);
        cudaFuncSetAttribute(o_proj_tc, cudaFuncAttributeMaxDynamicSharedMemorySize, gemm_smem);
        cudaFuncSetAttribute(q_proj_tc, cudaFuncAttributeMaxDynamicSharedMemorySize, qgemm_smem);
        cudaFuncSetAttribute(attn_tc, cudaFuncAttributeMaxDynamicSharedMemorySize, ATTN_SMEM);
        inited = 1;
    }

    zero_stats_kernel<<<(Bsz * HWs + 255) / 256, 256>>>();
    kv_proj_tc<<<dim3(4, 10, 2), 256, gemm_smem>>>(tf, wk, bk, wv, bv);
    q_proj_tc<<<dim3(4, 32, 16), 256, qgemm_smem>>>(x, wq, bq);
    attn_tc<<<dim3(32, 8, 16), 256, ATTN_SMEM>>>(g1, b1, g2, b2);
    o_proj_tc<<<dim3(32, 4, 16), 256, gemm_smem>>>(wo, bo, x, out);
}

// round 9
// speedup vs baseline: 1.4762x; 1.4762x over previous
#include <cuda_runtime.h>
#include <cstdint>

#define Bsz 16
#define Cch 512
#define HWs 4096
#define Lt  77
#define Dd  768
#define NHh 8
#define HDd 64

// ---------------- scratch (device globals; no allocation allowed) ----------------
__device__ float g_q[(size_t)Bsz * HWs * Cch];     // token-major [b][hw][c] (pre-LN)
__device__ float g_attn[(size_t)Bsz * HWs * Cch];  // attention output, token-major
__device__ float g_k[Bsz * Lt * Cch];              // token-major [b*l][c] (pre-LN)
__device__ float g_v[Bsz * Lt * Cch];
__device__ float g_qsum[Bsz * HWs];                // per-token sum / sumsq (atomic acc)
__device__ float g_qsq[Bsz * HWs];
__device__ float g_ksum[Bsz * Lt];
__device__ float g_ksq[Bsz * Lt];

// =====================================================================
// helpers
// =====================================================================
__device__ __forceinline__ void mma8(float* c, const uint32_t* a, const uint32_t* b) {
    asm volatile(
        "mma.sync.aligned.m16n8k8.row.col.f32.tf32.tf32.f32 "
        "{%0,%1,%2,%3}, {%4,%5,%6,%7}, {%8,%9}, {%0,%1,%2,%3};"
        : "+f"(c[0]), "+f"(c[1]), "+f"(c[2]), "+f"(c[3])
        : "r"(a[0]), "r"(a[1]), "r"(a[2]), "r"(a[3]), "r"(b[0]), "r"(b[1]));
}

__device__ __forceinline__ void cp16(uint32_t dst, const void* src) {
    asm volatile("cp.async.cg.shared.global [%0], [%1], 16;" :: "r"(dst), "l"(src));
}
__device__ __forceinline__ void cp16z(uint32_t dst, const void* src, bool pred) {
    int sz = pred ? 16 : 0;
    asm volatile("cp.async.cg.shared.global [%0], [%1], 16, %2;" :: "r"(dst), "l"(src), "r"(sz));
}
__device__ __forceinline__ void cp_commit() { asm volatile("cp.async.commit_group;"); }
__device__ __forceinline__ void cp_wait1() { asm volatile("cp.async.wait_group 1;"); }
__device__ __forceinline__ void cp_wait0() { asm volatile("cp.async.wait_group 0;"); }

#define AS_STR 36      // A smem [128][36] row-major m x k
#define BS_STR 36      // B smem [128][36] row-major n x k
#define AQ_STR 136     // q_proj A smem [32][136] k x m
#define STAGE_A (128 * AS_STR)
#define STAGE_B (128 * BS_STR)
#define STAGE_AQ (32 * AQ_STR)

// compute one k=32 chunk; A row-major [m][k] str 36, B row-major [n][k] str 36
__device__ __forceinline__ void mma_chunk(
    const uint32_t* __restrict__ As, const uint32_t* __restrict__ Bs,
    float cacc[4][4][4], int wm, int wn, int g, int tg)
{
    #pragma unroll
    for (int ks = 0; ks < 4; ks++) {
        uint32_t af[4][4], bf[4][2];
        #pragma unroll
        for (int mt = 0; mt < 4; mt++) {
            int base = (wm * 64 + mt * 16 + g) * AS_STR + ks * 8 + tg;
            af[mt][0] = As[base];
            af[mt][1] = As[base + 8 * AS_STR];
            af[mt][2] = As[base + 4];
            af[mt][3] = As[base + 8 * AS_STR + 4];
        }
        #pragma unroll
        for (int nt = 0; nt < 4; nt++) {
            int bb = (wn * 32 + nt * 8 + g) * BS_STR + ks * 8 + tg;
            bf[nt][0] = Bs[bb];
            bf[nt][1] = Bs[bb + 4];
        }
        #pragma unroll
        for (int mt = 0; mt < 4; mt++)
            #pragma unroll
            for (int nt = 0; nt < 4; nt++)
                mma8(cacc[mt][nt], af[mt], bf[nt]);
    }
}

// compute one k=32 chunk; A k-major [k][m] str 136, B row-major [n][k] str 36
__device__ __forceinline__ void mma_chunk_kmaj(
    const uint32_t* __restrict__ As, const uint32_t* __restrict__ Bs,
    float cacc[4][4][4], int wm, int wn, int g, int tg)
{
    #pragma unroll
    for (int ks = 0; ks < 4; ks++) {
        uint32_t af[4][4], bf[4][2];
        #pragma unroll
        for (int mt = 0; mt < 4; mt++) {
            int m = wm * 64 + mt * 16 + g;
            af[mt][0] = As[(ks * 8 + tg) * AQ_STR + m];
            af[mt][1] = As[(ks * 8 + tg) * AQ_STR + m + 8];
            af[mt][2] = As[(ks * 8 + tg + 4) * AQ_STR + m];
            af[mt][3] = As[(ks * 8 + tg + 4) * AQ_STR + m + 8];
        }
        #pragma unroll
        for (int nt = 0; nt < 4; nt++) {
            int bb = (wn * 32 + nt * 8 + g) * BS_STR + ks * 8 + tg;
            bf[nt][0] = Bs[bb];
            bf[nt][1] = Bs[bb + 4];
        }
        #pragma unroll
        for (int mt = 0; mt < 4; mt++)
            #pragma unroll
            for (int nt = 0; nt < 4; nt++)
                mma8(cacc[mt][nt], af[mt], bf[nt]);
    }
}

// quad-reduce (lanes sharing g, tg=0..3) then atomic accumulate row stats
__device__ __forceinline__ void stat_atomic(float s, float q, int tg, float* sumA, float* sqA) {
    s += __shfl_xor_sync(0xffffffffu, s, 1);
    s += __shfl_xor_sync(0xffffffffu, s, 2);
    q += __shfl_xor_sync(0xffffffffu, q, 1);
    q += __shfl_xor_sync(0xffffffffu, q, 2);
    if (tg == 0) { atomicAdd(sumA, s); atomicAdd(sqA, q); }
}

// =====================================================================
// zero stats accumulators
// =====================================================================
__global__ void zero_stats_kernel() {
    int i = blockIdx.x * 256 + threadIdx.x;
    if (i < Bsz * HWs) { g_qsum[i] = 0.f; g_qsq[i] = 0.f; }
    if (i < Bsz * Lt) { g_ksum[i] = 0.f; g_ksq[i] = 0.f; }
}

// =====================================================================
// KV projection (NT): C[m=token][n=c] = sum_d tf[m][d] * W[n][d] + bias[n]
// M=1232, N=512, K=768. grid (4, 10, 2) z: 0->k (+stats), 1->v.
// =====================================================================
__global__ __launch_bounds__(256, 2) void kv_proj_tc(
    const float* __restrict__ tf,
    const float* __restrict__ wk, const float* __restrict__ bk,
    const float* __restrict__ wv, const float* __restrict__ bv)
{
    const int M = Bsz * Lt;
    const float* W; const float* bias; float* out;
    if (blockIdx.z == 0) { W = wk; bias = bk; out = g_k; }
    else                 { W = wv; bias = bv; out = g_v; }

    extern __shared__ uint32_t dsm[];
    uint32_t* Asm[3] = { dsm, dsm + (STAGE_A + STAGE_B), dsm + 2 * (STAGE_A + STAGE_B) };
    uint32_t* Bsm[3] = { dsm + STAGE_A, dsm + (STAGE_A + STAGE_B) + STAGE_A,
                         dsm + 2 * (STAGE_A + STAGE_B) + STAGE_A };

    const int m0 = blockIdx.y * 128, n0 = blockIdx.x * 128;
    const int tid = threadIdx.x, lane = tid & 31, wid = tid >> 5;
    const int wm = wid & 1, wn = wid >> 1;
    const int g = lane >> 2, tg = lane & 3;
    const int r = tid >> 3, c4 = (tid & 7) << 2;
    float cacc[4][4][4] = {};

    auto load_stage = [&](int st, int k0) {
        #pragma unroll
        for (int u = 0; u < 4; u++) {
            int rr = r + u * 32;
            uint32_t da = __cvta_generic_to_shared(&Asm[st][rr * AS_STR + c4]);
            cp16z(da, tf + (size_t)(m0 + rr) * Dd + k0 + c4, (m0 + rr) < M);
            uint32_t db = __cvta_generic_to_shared(&Bsm[st][rr * BS_STR + c4]);
            cp16(db, W + (size_t)(n0 + rr) * Dd + k0 + c4);
        }
        cp_commit();
    };

    const int NCH = Dd / 32;
    load_stage(0, 0);
    load_stage(1, 32);
    for (int ch = 0; ch < NCH; ch++) {
        if (ch < NCH - 1) cp_wait1(); else cp_wait0();
        __syncthreads();
        if (ch + 2 < NCH) load_stage((ch + 2) % 3, (ch + 2) * 32);
        mma_chunk(Asm[ch % 3], Bsm[ch % 3], cacc, wm, wn, g, tg);
    }

    float s0[4] = {}, q0[4] = {}, s1[4] = {}, q1[4] = {};
    #pragma unroll
    for (int mt = 0; mt < 4; mt++) {
        #pragma unroll
        for (int nt = 0; nt < 4; nt++) {
            int m = m0 + wm * 64 + mt * 16 + g;
            int n = n0 + wn * 32 + nt * 8 + tg * 2;
            float2 bb = *(const float2*)(bias + n);
            float2 r0 = make_float2(cacc[mt][nt][0] + bb.x, cacc[mt][nt][1] + bb.y);
            float2 r1 = make_float2(cacc[mt][nt][2] + bb.x, cacc[mt][nt][3] + bb.y);
            if (m < M) *(float2*)(out + (size_t)m * Cch + n) = r0;
            if (m + 8 < M) *(float2*)(out + (size_t)(m + 8) * Cch + n) = r1;
            s0[mt] += r0.x + r0.y; q0[mt] += r0.x * r0.x + r0.y * r0.y;
            s1[mt] += r1.x + r1.y; q1[mt] += r1.x * r1.x + r1.y * r1.y;
        }
    }
    if (blockIdx.z == 0) {
        #pragma unroll
        for (int mt = 0; mt < 4; mt++) {
            int m = m0 + wm * 64 + mt * 16 + g;
            if (m < M) stat_atomic(s0[mt], q0[mt], tg, &g_ksum[m], &g_ksq[m]);
            if (m + 8 < M) stat_atomic(s1[mt], q1[mt], tg, &g_ksum[m + 8], &g_ksq[m + 8]);
        }
    }
}

// =====================================================================
// Q projection, token-major output + LN stats:
// C[m=token][n=chan] = sum_c X[c][m] * wq[n][c] + bq[n] + 0.05*pe(n,m)
// M=4096, N=512, K=512. grid (4, 32, 16).
// =====================================================================
__global__ __launch_bounds__(256, 2) void q_proj_tc(
    const float* __restrict__ x, const float* __restrict__ wq, const float* __restrict__ bq)
{
    const int b = blockIdx.z;
    const float* X = x + (size_t)b * Cch * HWs;
    float* out = g_q + (size_t)b * HWs * Cch;

    extern __shared__ uint32_t dsm[];
    uint32_t* Asm[3] = { dsm, dsm + (STAGE_AQ + STAGE_B), dsm + 2 * (STAGE_AQ + STAGE_B) };
    uint32_t* Bsm[3] = { dsm + STAGE_AQ, dsm + (STAGE_AQ + STAGE_B) + STAGE_AQ,
                         dsm + 2 * (STAGE_AQ + STAGE_B) + STAGE_AQ };

    const int m0 = blockIdx.y * 128, n0 = blockIdx.x * 128;
    const int tid = threadIdx.x, lane = tid & 31, wid = tid >> 5;
    const int wm = wid & 1, wn = wid >> 1;
    const int g = lane >> 2, tg = lane & 3;
    const int kk = tid >> 5, mc4 = (tid & 31) << 2;
    const int r = tid >> 3, c4 = (tid & 7) << 2;
    float cacc[4][4][4] = {};

    auto load_stage = [&](int st, int k0) {
        #pragma unroll
        for (int u = 0; u < 4; u++) {
            int kr = kk + u * 8;
            uint32_t da = __cvta_generic_to_shared(&Asm[st][kr * AQ_STR + mc4]);
            cp16(da, X + (size_t)(k0 + kr) * HWs + m0 + mc4);
            int rr = r + u * 32;
            uint32_t db = __cvta_generic_to_shared(&Bsm[st][rr * BS_STR + c4]);
            cp16(db, wq + (size_t)(n0 + rr) * Cch + k0 + c4);
        }
        cp_commit();
    };

    const int NCH = Cch / 32;
    load_stage(0, 0);
    load_stage(1, 32);
    for (int ch = 0; ch < NCH; ch++) {
        if (ch < NCH - 1) cp_wait1(); else cp_wait0();
        __syncthreads();
        if (ch + 2 < NCH) load_stage((ch + 2) % 3, (ch + 2) * 32);
        mma_chunk_kmaj(Asm[ch % 3], Bsm[ch % 3], cacc, wm, wn, g, tg);
    }

    const float pes = 0.05f / 63.0f;
    float s0[4] = {}, q0[4] = {}, s1[4] = {}, q1[4] = {};
    #pragma unroll
    for (int mt = 0; mt < 4; mt++) {
        #pragma unroll
        for (int nt = 0; nt < 4; nt++) {
            int m = m0 + wm * 64 + mt * 16 + g;     // token
            int n = n0 + wn * 32 + nt * 8 + tg * 2; // channel
            float2 bb = *(const float2*)(bq + n);
            bool use_x = n < (Cch / 2);
            float pe0 = pes * (float)(use_x ? (m & 63) : ((m >> 6) & 63));
            float pe1 = pes * (float)(use_x ? ((m + 8) & 63) : (((m + 8) >> 6) & 63));
            float2 r0 = make_float2(cacc[mt][nt][0] + bb.x + pe0, cacc[mt][nt][1] + bb.y + pe0);
            float2 r1 = make_float2(cacc[mt][nt][2] + bb.x + pe1, cacc[mt][nt][3] + bb.y + pe1);
            *(float2*)(out + (size_t)m * Cch + n) = r0;
            *(float2*)(out + (size_t)(m + 8) * Cch + n) = r1;
            s0[mt] += r0.x + r0.y; q0[mt] += r0.x * r0.x + r0.y * r0.y;
            s1[mt] += r1.x + r1.y; q1[mt] += r1.x * r1.x + r1.y * r1.y;
        }
    }
    #pragma unroll
    for (int mt = 0; mt < 4; mt++) {
        int m = m0 + wm * 64 + mt * 16 + g;
        size_t row = (size_t)b * HWs + m;
        stat_atomic(s0[mt], q0[mt], tg, &g_qsum[row], &g_qsq[row]);
        stat_atomic(s1[mt], q1[mt], tg, &g_qsum[row + 8], &g_qsq[row + 8]);
    }
}

// =====================================================================
// Output projection + bias + residual (mma.sync, 3-stage):
// C[m=chan][n=token] = sum_c wo[m][c] * g_attn[n][c] + bo[m] + x[b][m][n]
// M=512, N=4096, K=512. grid (32, 4, 16).
// =====================================================================
__global__ __launch_bounds__(256, 2) void o_proj_tc(
    const float* __restrict__ wo, const float* __restrict__ bo,
    const float* __restrict__ x, float* __restrict__ outp)
{
    const int b = blockIdx.z;
    const float* Bm = g_attn + (size_t)b * HWs * Cch;

    extern __shared__ uint32_t dsm[];
    uint32_t* Asm[3] = { dsm, dsm + (STAGE_A + STAGE_B), dsm + 2 * (STAGE_A + STAGE_B) };
    uint32_t* Bsm[3] = { dsm + STAGE_A, dsm + (STAGE_A + STAGE_B) + STAGE_A,
                         dsm + 2 * (STAGE_A + STAGE_B) + STAGE_A };

    const int m0 = blockIdx.y * 128, n0 = blockIdx.x * 128;
    const int tid = threadIdx.x, lane = tid & 31, wid = tid >> 5;
    const int wm = wid & 1, wn = wid >> 1;
    const int g = lane >> 2, tg = lane & 3;
    const int r = tid >> 3, c4 = (tid & 7) << 2;
    float cacc[4][4][4] = {};

    auto load_stage = [&](int st, int k0) {
        #pragma unroll
        for (int u = 0; u < 4; u++) {
            int rr = r + u * 32;
            uint32_t da = __cvta_generic_to_shared(&Asm[st][rr * AS_STR + c4]);
            cp16(da, wo + (size_t)(m0 + rr) * Cch + k0 + c4);
            uint32_t db = __cvta_generic_to_shared(&Bsm[st][rr * BS_STR + c4]);
            cp16(db, Bm + (size_t)(n0 + rr) * Cch + k0 + c4);
        }
        cp_commit();
    };

    const int NCH = Cch / 32;
    load_stage(0, 0);
    load_stage(1, 32);
    for (int ch = 0; ch < NCH; ch++) {
        if (ch < NCH - 1) cp_wait1(); else cp_wait0();
        __syncthreads();
        if (ch + 2 < NCH) load_stage((ch + 2) % 3, (ch + 2) * 32);
        mma_chunk(Asm[ch % 3], Bsm[ch % 3], cacc, wm, wn, g, tg);
    }

    #pragma unroll
    for (int mt = 0; mt < 4; mt++) {
        #pragma unroll
        for (int nt = 0; nt < 4; nt++) {
            int m = m0 + wm * 64 + mt * 16 + g;     // channel
            int n = n0 + wn * 32 + nt * 8 + tg * 2; // token
            float bo0 = bo[m], bo1 = bo[m + 8];
            size_t i0 = (size_t)b * Cch * HWs + (size_t)m * HWs + n;
            size_t i1 = (size_t)b * Cch * HWs + (size_t)(m + 8) * HWs + n;
            float2 x0 = *(const float2*)(x + i0);
            float2 x1 = *(const float2*)(x + i1);
            float2 r0 = make_float2(cacc[mt][nt][0] + bo0 + x0.x, cacc[mt][nt][1] + bo0 + x0.y);
            float2 r1 = make_float2(cacc[mt][nt][2] + bo1 + x1.x, cacc[mt][nt][3] + bo1 + x1.y);
            *(float2*)(outp + i0) = r0;
            *(float2*)(outp + i1) = r1;
        }
    }
}

// =====================================================================
// Tensor-core attention, LN(Q)/LN(K) fused, P in registers,
// softmax without max-subtraction (LN-bounded scores).
// block = 128 q tokens x head x batch. grid (32, 8, 16), 256 threads.
// =====================================================================
#define QS_STR 68
#define KS_STR 68
#define VS_STR 68
#define ATTN_SMEM ((128 * QS_STR + 80 * KS_STR + 80 * VS_STR + 128 + 128 + 80 + 80) * 4)

__global__ __launch_bounds__(256) void attn_tc(
    const float* __restrict__ g1, const float* __restrict__ b1,
    const float* __restrict__ g2, const float* __restrict__ b2)
{
    extern __shared__ float sm[];
    float* Qs = sm;
    float* Ks = Qs + 128 * QS_STR;
    float* Vs = Ks + 80 * KS_STR;
    float* qmu = Vs + 80 * VS_STR;
    float* qrs = qmu + 128;
    float* kmu = qrs + 128;
    float* krs = kmu + 80;

    const int tid = threadIdx.x, lane = tid & 31, w = tid >> 5;
    const int g = lane >> 2, tg = lane & 3;
    const int t0 = blockIdx.x * 128, h = blockIdx.y, b = blockIdx.z;

    if (tid < 128) {
        size_t row = (size_t)b * HWs + t0 + tid;
        float s = g_qsum[row], q = g_qsq[row];
        float m = s * (1.0f / 512.0f);
        qmu[tid] = m;
        qrs[tid] = rsqrtf(q * (1.0f / 512.0f) - m * m + 1e-5f);
    } else if (tid < 128 + 80) {
        int l = tid - 128;
        float m = 0.f, r = 0.f;
        if (l < Lt) {
            size_t row = (size_t)b * Lt + l;
            float s = g_ksum[row], q = g_ksq[row];
            m = s * (1.0f / 512.0f);
            r = rsqrtf(q * (1.0f / 512.0f) - m * m + 1e-5f);
        }
        kmu[l] = m; krs[l] = r;
    }
    __syncthreads();

    const float* qb = g_q + ((size_t)b * HWs + t0) * Cch + h * HDd;
    for (int f = tid; f < 128 * 16; f += 256) {
        int t = f >> 4, dc = (f & 15) << 2;
        float4 v = *(const float4*)(qb + (size_t)t * Cch + dc);
        float4 gg = *(const float4*)(g1 + h * HDd + dc);
        float4 bb = *(const float4*)(b1 + h * HDd + dc);
        float m = qmu[t], r = qrs[t];
        float* d = Qs + t * QS_STR + dc;
        d[0] = (v.x - m) * r * gg.x + bb.x;
        d[1] = (v.y - m) * r * gg.y + bb.y;
        d[2] = (v.z - m) * r * gg.z + bb.z;
        d[3] = (v.w - m) * r * gg.w + bb.w;
    }
    const float* kb = g_k + (size_t)b * Lt * Cch + h * HDd;
    const float* vb = g_v + (size_t)b * Lt * Cch + h * HDd;
    for (int f = tid; f < 80 * 16; f += 256) {
        int l = f >> 4, dc = (f & 15) << 2;
        float* kd = Ks + l * KS_STR + dc;
        float* vd = Vs + l * VS_STR + dc;
        if (l < Lt) {
            float4 k4 = *(const float4*)(kb + (size_t)l * Cch + dc);
            float4 v4 = *(const float4*)(vb + (size_t)l * Cch + dc);
            float4 gg = *(const float4*)(g2 + h * HDd + dc);
            float4 bb = *(const float4*)(b2 + h * HDd + dc);
            float m = kmu[l], r = krs[l];
            kd[0] = (k4.x - m) * r * gg.x + bb.x;
            kd[1] = (k4.y - m) * r * gg.y + bb.y;
            kd[2] = (k4.z - m) * r * gg.z + bb.z;
            kd[3] = (k4.w - m) * r * gg.w + bb.w;
            vd[0] = v4.x; vd[1] = v4.y; vd[2] = v4.z; vd[3] = v4.w;
        } else {
            kd[0] = kd[1] = kd[2] = kd[3] = 0.f;
            vd[0] = vd[1] = vd[2] = vd[3] = 0.f;
        }
    }
    __syncthreads();

    const uint32_t* Qu = (const uint32_t*)Qs;
    const uint32_t* Ku = (const uint32_t*)Ks;
    const uint32_t* Vu = (const uint32_t*)Vs;

    // ---- S = Q K^T
    float sfr[10][4] = {};
    #pragma unroll
    for (int ks = 0; ks < 8; ks++) {
        uint32_t aq[4];
        int ab = (w * 16 + g) * QS_STR + ks * 8 + tg;
        aq[0] = Qu[ab];
        aq[1] = Qu[ab + 8 * QS_STR];
        aq[2] = Qu[ab + 4];
        aq[3] = Qu[ab + 8 * QS_STR + 4];
        #pragma unroll
        for (int nt = 0; nt < 10; nt++) {
            uint32_t bf[2];
            int bb = (nt * 8 + g) * KS_STR + ks * 8 + tg;
            bf[0] = Ku[bb];
            bf[1] = Ku[bb + 4];
            mma8(sfr[nt], aq, bf);
        }
    }

    // ---- softmax without max-subtraction (post-LN scores are O(1))
    float sum0 = 0.f, sum1 = 0.f;
    #pragma unroll
    for (int nt = 0; nt < 10; nt++) {
        int c0 = nt * 8 + tg * 2, c1 = c0 + 1;
        float e00 = (c0 < Lt) ? __expf(sfr[nt][0] * 0.125f) : 0.f;
        float e01 = (c1 < Lt) ? __expf(sfr[nt][1] * 0.125f) : 0.f;
        float e10 = (c0 < Lt) ? __expf(sfr[nt][2] * 0.125f) : 0.f;
        float e11 = (c1 < Lt) ? __expf(sfr[nt][3] * 0.125f) : 0.f;
        sum0 += e00 + e01; sum1 += e10 + e11;
        sfr[nt][0] = e00; sfr[nt][1] = e01; sfr[nt][2] = e10; sfr[nt][3] = e11;
    }
    sum0 += __shfl_xor_sync(0xffffffffu, sum0, 1);
    sum0 += __shfl_xor_sync(0xffffffffu, sum0, 2);
    sum1 += __shfl_xor_sync(0xffffffffu, sum1, 1);
    sum1 += __shfl_xor_sync(0xffffffffu, sum1, 2);
    float inv0 = 1.0f / sum0, inv1 = 1.0f / sum1;

    // ---- O = P V: c-frag -> a-frag via quad shuffles
    float ofr[8][4] = {};
    const int src1 = (lane & ~3) | (tg >> 1);
    const int src2 = src1 + 2;
    #pragma unroll
    for (int kt = 0; kt < 10; kt++) {
        float v00 = __shfl_sync(0xffffffffu, sfr[kt][0], src1);
        float v01 = __shfl_sync(0xffffffffu, sfr[kt][1], src1);
        float v20 = __shfl_sync(0xffffffffu, sfr[kt][0], src2);
        float v21 = __shfl_sync(0xffffffffu, sfr[kt][1], src2);
        float v10 = __shfl_sync(0xffffffffu, sfr[kt][2], src1);
        float v11 = __shfl_sync(0xffffffffu, sfr[kt][3], src1);
        float v30 = __shfl_sync(0xffffffffu, sfr[kt][2], src2);
        float v31 = __shfl_sync(0xffffffffu, sfr[kt][3], src2);
        bool odd = (tg & 1);
        uint32_t ap[4];
        ap[0] = __float_as_uint(odd ? v01 : v00);
        ap[1] = __float_as_uint(odd ? v11 : v10);
        ap[2] = __float_as_uint(odd ? v21 : v20);
        ap[3] = __float_as_uint(odd ? v31 : v30);
        #pragma unroll
        for (int nt = 0; nt < 8; nt++) {
            uint32_t bf[2];
            bf[0] = Vu[(kt * 8 + tg) * VS_STR + nt * 8 + g];
            bf[1] = Vu[(kt * 8 + tg + 4) * VS_STR + nt * 8 + g];
            mma8(ofr[nt], ap, bf);
        }
    }

    float* ob = g_attn + ((size_t)b * HWs + t0 + w * 16) * Cch + h * HDd;
    #pragma unroll
    for (int nt = 0; nt < 8; nt++) {
        int n = nt * 8 + tg * 2;
        float2 r0 = make_float2(ofr[nt][0] * inv0, ofr[nt][1] * inv0);
        float2 r1 = make_float2(ofr[nt][2] * inv1, ofr[nt][3] * inv1);
        *(float2*)(ob + (size_t)g * Cch + n) = r0;
        *(float2*)(ob + (size_t)(g + 8) * Cch + n) = r1;
    }
}

// =====================================================================
extern "C" void kernel_launch(void* const* d_in, const int* in_sizes, int n_in,
                              void* d_out, int out_size)
{
    const float* x  = (const float*)d_in[0];
    const float* tf = (const float*)d_in[1];
    const float* wq = (const float*)d_in[2];
    const float* bq = (const float*)d_in[3];
    const float* wk = (const float*)d_in[4];
    const float* bk = (const float*)d_in[5];
    const float* wv = (const float*)d_in[6];
    const float* bv = (const float*)d_in[7];
    const float* wo = (const float*)d_in[8];
    const float* bo = (const float*)d_in[9];
    const float* g1 = (const float*)d_in[10];
    const float* b1 = (const float*)d_in[11];
    const float* g2 = (const float*)d_in[12];
    const float* b2 = (const float*)d_in[13];
    float* out = (float*)d_out;

    const int gemm_smem = 3 * (STAGE_A + STAGE_B) * 4;
    const int qgemm_smem = 3 * (STAGE_AQ + STAGE_B) * 4;
    cudaFuncSetAttribute(kv_proj_tc, cudaFuncAttributeMaxDynamicSharedMemorySize, gemm_smem);
    cudaFuncSetAttribute(q_proj_tc, cudaFuncAttributeMaxDynamicSharedMemorySize, qgemm_smem);
    cudaFuncSetAttribute(o_proj_tc, cudaFuncAttributeMaxDynamicSharedMemorySize, gemm_smem);
    cudaFuncSetAttribute(attn_tc, cudaFuncAttributeMaxDynamicSharedMemorySize, ATTN_SMEM);

    zero_stats_kernel<<<(Bsz * HWs + 255) / 256, 256>>>();
    kv_proj_tc<<<dim3(4, 10, 2), 256, gemm_smem>>>(tf, wk, bk, wv, bv);
    q_proj_tc<<<dim3(4, 32, 16), 256, qgemm_smem>>>(x, wq, bq);
    attn_tc<<<dim3(32, 8, 16), 256, ATTN_SMEM>>>(g1, b1, g2, b2);
    o_proj_tc<<<dim3(32, 4, 16), 256, gemm_smem>>>(wo, bo, x, out);
}